// round 13
// baseline (speedup 1.0000x reference)
#include <cuda_runtime.h>
#include <cstdint>

#define NGS 10
typedef unsigned long long u64;

constexpr int IN_COLS    = 4 * NGS;            // 40
constexpr int OUT_COLS   = 6 * NGS;            // 60
constexpr int THREADS    = 128;                // 4 warps, 1 row/thread
constexpr int ROWS_PER_BLOCK = 128;
constexpr int BUF_FLOATS = ROWS_PER_BLOCK * OUT_COLS;   // 7680 fl = 30720 B overlay
constexpr int IN_BYTES   = ROWS_PER_BLOCK * IN_COLS * 4;   // 20480 B contiguous
constexpr int OUT_BYTES  = ROWS_PER_BLOCK * OUT_COLS * 4;  // 30720 B contiguous

// ---- packed f32x2 helpers (sm_100+) ----
__device__ __forceinline__ u64 pk2(float a, float b) {
    u64 r; asm("mov.b64 %0, {%1,%2};" : "=l"(r) : "f"(a), "f"(b)); return r;
}
__device__ __forceinline__ void up2(u64 v, float& a, float& b) {
    asm("mov.b64 {%0,%1}, %2;" : "=f"(a), "=f"(b) : "l"(v));
}
__device__ __forceinline__ u64 mul2(u64 a, u64 b) {
    u64 r; asm("mul.rn.f32x2 %0, %1, %2;" : "=l"(r) : "l"(a), "l"(b)); return r;
}
__device__ __forceinline__ u64 add2(u64 a, u64 b) {
    u64 r; asm("add.rn.f32x2 %0, %1, %2;" : "=l"(r) : "l"(a), "l"(b)); return r;
}
__device__ __forceinline__ u64 fma2_(u64 a, u64 b, u64 c) {
    u64 r; asm("fma.rn.f32x2 %0, %1, %2, %3;" : "=l"(r) : "l"(a), "l"(b), "l"(c)); return r;
}

__device__ __forceinline__ u64 mk_evict_first_policy() {
    u64 p; asm("createpolicy.fractional.L2::evict_first.b64 %0, 1.0;" : "=l"(p));
    return p;
}

__global__ __launch_bounds__(THREADS, 7)
void kmap_kernel(const float* __restrict__ var,
                 const float* __restrict__ slider_lengths,
                 const float* __restrict__ scos_g,
                 const float* __restrict__ ssin_g,
                 const float* __restrict__ note_dist,
                 const float* __restrict__ tick_diff,
                 const float* __restrict__ start_pos,
                 const int*   __restrict__ is_slider,
                 float* __restrict__ out,
                 int B)
{
    __shared__ float  sBuf[BUF_FLOATS];   // overlay: in raw 20480B / out raw 30720B
    __shared__ u64    s_mbar;             // mbarrier for bulk input load
    __shared__ float4 s_wall[NGS];        // wl, wr, wt, wb
    __shared__ float4 s_rot[NGS];         // scos, ssin, sln, isl_flag
    __shared__ u64    s_l2[NGS], s_rr2[NGS], s_nr2[NGS];
    __shared__ float2 s_p0;

    const int tid      = threadIdx.x;
    const int blockRow = blockIdx.x * ROWS_PER_BLOCK;
    const int rows     = (B - blockRow) < ROWS_PER_BLOCK ? (B - blockRow) : ROWS_PER_BLOCK;
    const u64 pol      = mk_evict_first_policy();
    const uint32_t mbar = (uint32_t)__cvta_generic_to_shared(&s_mbar);
    const uint32_t sIn  = (uint32_t)__cvta_generic_to_shared(sBuf);

    // ---- one 20KB TMA bulk input load, issued FIRST ----
    if (rows == ROWS_PER_BLOCK) {
        if (tid == 0) {
            asm volatile("mbarrier.init.shared.b64 [%0], 1;" :: "r"(mbar) : "memory");
            asm volatile("mbarrier.arrive.expect_tx.shared.b64 _, [%0], %1;"
                         :: "r"(mbar), "r"(IN_BYTES) : "memory");
            const float* gsrc = var + (size_t)blockRow * IN_COLS;
            asm volatile(
                "cp.async.bulk.shared::cluster.global.mbarrier::complete_tx::bytes"
                ".L2::cache_hint [%0], [%1], %2, [%3], %4;"
                :: "r"(sIn), "l"(gsrc), "r"((uint32_t)IN_BYTES), "r"(mbar), "l"(pol)
                : "memory");
        }
    }

    // ---- packed per-group params (overlaps bulk-load latency) ----
    if (tid < NGS) {
        float l  = note_dist[tid];                        // LMUL = 1.0
        float rr = (tick_diff[tid] <= 1.0f) ? 0.0f : 1.0f;
        s_wall[tid] = make_float4(0.05f * 512.0f + 0.5f * l,
                                  0.95f * 512.0f - 0.5f * l,
                                  0.05f * 384.0f + 0.5f * l,
                                  0.95f * 384.0f - 0.5f * l);
        s_rot[tid]  = make_float4(scos_g[tid], ssin_g[tid],
                                  slider_lengths[tid],
                                  is_slider[tid] ? 1.0f : 0.0f);
        s_l2[tid]  = pk2(l, l);
        s_rr2[tid] = pk2(rr, rr);
        s_nr2[tid] = pk2(1.0f - rr, 1.0f - rr);
    }
    if (tid == 0) s_p0 = make_float2(start_pos[0], start_pos[1]);
    __syncthreads();

    if (rows == ROWS_PER_BLOCK) {
        // ---- wait bulk load completion (all threads) ----
        {
            uint32_t done;
            asm volatile(
                "{\n\t.reg .pred p;\n\t"
                "mbarrier.try_wait.parity.acquire.cta.shared::cta.b64 p, [%1], %2;\n\t"
                "selp.b32 %0, 1, 0, p;\n\t}"
                : "=r"(done) : "r"(mbar), "r"(0u) : "memory");
            while (!done) {
                asm volatile(
                    "{\n\t.reg .pred p;\n\t"
                    "mbarrier.try_wait.parity.acquire.cta.shared::cta.b64 p, [%1], %2, 0x989680;\n\t"
                    "selp.b32 %0, 1, 0, p;\n\t}"
                    : "=r"(done) : "r"(mbar), "r"(0u) : "memory");
            }
        }

        // ---- stage inputs to registers: 10 x LDS.128 from raw stride-40 rows ----
        float rin[IN_COLS];
        const float* rowp = sBuf + tid * IN_COLS;   // tid*160B (2-way LDS conflict, ok)
        #pragma unroll
        for (int c = 0; c < IN_COLS / 4; ++c) {
            float4 t = *reinterpret_cast<const float4*>(rowp + 4 * c);
            rin[4*c+0] = t.x; rin[4*c+1] = t.y; rin[4*c+2] = t.z; rin[4*c+3] = t.w;
        }
        __syncthreads();   // all threads staged before STS overwrites the overlay

        // ---- compute: packed f32x2 scan; k-pairs emitted as 3x STS.128 ----
        const u64 CA   = pk2(256.0f, 192.0f);
        const u64 CINV = pk2(1.0f / 512.0f, 1.0f / 384.0f);
        float* orow = sBuf + tid * OUT_COLS;        // raw stride 60, 240B row base
        float px = s_p0.x, py = s_p0.y;
        u64 pxy = pk2(px, py);
        #pragma unroll
        for (int kp = 0; kp < NGS / 2; ++kp) {
            float o[12];
            #pragma unroll
            for (int h = 0; h < 2; ++h) {
                const int k = 2 * kp + h;
                float4 wall = s_wall[k];
                float4 rot  = s_rot[k];
                u64 l2 = s_l2[k], rr2 = s_rr2[k], nr2 = s_nr2[k];

                float vk   = rin[k],           vkh  = rin[NGS + k];
                float v2k  = rin[2 * NGS + k], v2kh = rin[3 * NGS + k];

                float inv  = rsqrtf(fmaf(vk,  vk,  v2k  * v2k));
                float invh = rsqrtf(fmaf(vkh, vkh, v2kh * v2kh));
                u64 pv  = pk2(vk, v2k);
                u64 cs  = mul2(pv, pk2(inv, inv));               // (ck, sk)
                u64 csh = mul2(pk2(vkh, v2kh), pk2(invh, invh)); // (ckh, skh)

                float dx, dy; up2(mul2(l2, cs), dx, dy);
                float xd = (px < wall.x) ?  fabsf(dx)
                         : (px > wall.y) ? -fabsf(dx)
                         : ((px > wall.x) && (px < wall.y)) ? dx : 0.0f;
                float yd = (py < wall.z) ?  fabsf(dy)
                         : (py > wall.w) ? -fabsf(dy)
                         : ((py > wall.z) && (py < wall.w)) ? dy : 0.0f;

                u64 rer = fma2_(pv, CA, CA);
                u64 xy  = fma2_(nr2, add2(pxy, pk2(xd, yd)), mul2(rr2, rer));
                u64 c01 = mul2(xy, CINV);
                pxy = xy;
                up2(xy, px, py);
                float c0, c1; up2(c01, c0, c1);

                float c2, c3, c4, c5;
                if (rot.w != 0.0f) {     // uniform per k
                    float ckh, skh; up2(csh, ckh, skh);
                    c2 = fmaf(ckh, rot.x, -(skh * rot.y));
                    c3 = fmaf(ckh, rot.y,  skh * rot.x);
                    up2(mul2(fma2_(csh, pk2(rot.z, rot.z), xy), CINV), c4, c5);
                } else {
                    up2(fma2_(nr2, cs, mul2(rr2, csh)), c2, c3);
                    c4 = c0; c5 = c1;
                }
                o[6*h+0] = c0; o[6*h+1] = c1; o[6*h+2] = c2;
                o[6*h+3] = c3; o[6*h+4] = c4; o[6*h+5] = c5;
            }
            float4* dst = reinterpret_cast<float4*>(orow + 12 * kp);  // 48B-aligned
            dst[0] = make_float4(o[0], o[1], o[2],  o[3]);
            dst[1] = make_float4(o[4], o[5], o[6],  o[7]);
            dst[2] = make_float4(o[8], o[9], o[10], o[11]);
        }

        // ---- one 30KB TMA bulk store (evict-first), smem raw -> global ----
        asm volatile("fence.proxy.async.shared::cta;" ::: "memory");
        __syncthreads();
        if (tid == 0) {
            float* g = out + (size_t)blockRow * OUT_COLS;   // contiguous 30720B
            asm volatile("cp.async.bulk.global.shared::cta.bulk_group.L2::cache_hint "
                         "[%0], [%1], %2, %3;"
                         :: "l"(g), "r"(sIn), "n"(OUT_BYTES), "l"(pol) : "memory");
            asm volatile("cp.async.bulk.commit_group;" ::: "memory");
            asm volatile("cp.async.bulk.wait_group 0;" ::: "memory");
        }
    } else if (tid < rows) {
        // ---- partial tile fallback: direct scalar global path ----
        const float* grow  = var + (size_t)(blockRow + tid) * IN_COLS;
        float*       gorow = out + (size_t)(blockRow + tid) * OUT_COLS;
        float px = s_p0.x, py = s_p0.y;
        #pragma unroll
        for (int k = 0; k < NGS; ++k) {
            float4 wall = s_wall[k];
            float4 rot  = s_rot[k];
            float l, dum, rr;
            up2(s_l2[k], l, dum);
            up2(s_rr2[k], rr, dum);
            float nr = 1.0f - rr;
            float vk   = grow[k];
            float vkh  = grow[NGS + k];
            float v2k  = grow[2 * NGS + k];
            float v2kh = grow[3 * NGS + k];
            float inv  = rsqrtf(fmaf(vk, vk, v2k * v2k));
            float ck   = vk  * inv,  sk  = v2k  * inv;
            float invh = rsqrtf(fmaf(vkh, vkh, v2kh * v2kh));
            float ckh  = vkh * invh, skh = v2kh * invh;
            float dx = l * ck, dy = l * sk;
            float xd = (px < wall.x) ?  fabsf(dx)
                     : (px > wall.y) ? -fabsf(dx)
                     : ((px > wall.x) && (px < wall.y)) ? dx : 0.0f;
            float yd = (py < wall.z) ?  fabsf(dy)
                     : (py > wall.w) ? -fabsf(dy)
                     : ((py > wall.z) && (py < wall.w)) ? dy : 0.0f;
            float x = rr * (256.0f + 256.0f * vk)  + nr * (px + xd);
            float y = rr * (192.0f + 192.0f * v2k) + nr * (py + yd);
            float c0 = x * (1.0f / 512.0f), c1 = y * (1.0f / 384.0f);
            float c2, c3, c4, c5;
            if (rot.w != 0.0f) {
                c2 = ckh * rot.x - skh * rot.y;
                c3 = ckh * rot.y + skh * rot.x;
                c4 = (x + ckh * rot.z) * (1.0f / 512.0f);
                c5 = (y + skh * rot.z) * (1.0f / 384.0f);
            } else {
                c2 = rr * ckh + nr * ck;
                c3 = rr * skh + nr * sk;
                c4 = c0; c5 = c1;
            }
            gorow[6*k+0] = c0; gorow[6*k+1] = c1; gorow[6*k+2] = c2;
            gorow[6*k+3] = c3; gorow[6*k+4] = c4; gorow[6*k+5] = c5;
            px = x; py = y;
        }
    }
}

extern "C" void kernel_launch(void* const* d_in, const int* in_sizes, int n_in,
                              void* d_out, int out_size)
{
    const float* var  = (const float*)d_in[0];
    const float* sln  = (const float*)d_in[1];
    const float* scos = (const float*)d_in[2];
    const float* ssin = (const float*)d_in[3];
    const float* nd   = (const float*)d_in[4];
    const float* td   = (const float*)d_in[5];
    const float* sp   = (const float*)d_in[6];
    const int*   isl  = (const int*)d_in[7];
    float* out = (float*)d_out;

    int B = in_sizes[0] / IN_COLS;
    int blocks = (B + ROWS_PER_BLOCK - 1) / ROWS_PER_BLOCK;
    kmap_kernel<<<blocks, THREADS>>>(var, sln, scos, ssin, nd, td,
                                     sp, isl, out, B);
}

// round 14
// speedup vs baseline: 1.0307x; 1.0307x over previous
#include <cuda_runtime.h>
#include <cstdint>

#define NGS 10
typedef unsigned long long u64;

constexpr int IN_COLS    = 4 * NGS;        // 40
constexpr int OUT_COLS   = 6 * NGS;        // 60
constexpr int IN_STRIDE  = 44;             // mult of 4 (16B rows), conflict-free LDS.128
constexpr int THREADS    = 32;             // one warp per block
constexpr int BUF_FLOATS = 32 * OUT_COLS;  // 1920: overlaid in(1408)/out(1920)

// ---- packed f32x2 helpers (sm_100+) ----
__device__ __forceinline__ u64 pk2(float a, float b) {
    u64 r; asm("mov.b64 %0, {%1,%2};" : "=l"(r) : "f"(a), "f"(b)); return r;
}
__device__ __forceinline__ void up2(u64 v, float& a, float& b) {
    asm("mov.b64 {%0,%1}, %2;" : "=f"(a), "=f"(b) : "l"(v));
}
__device__ __forceinline__ u64 mul2(u64 a, u64 b) {
    u64 r; asm("mul.rn.f32x2 %0, %1, %2;" : "=l"(r) : "l"(a), "l"(b)); return r;
}
__device__ __forceinline__ u64 add2(u64 a, u64 b) {
    u64 r; asm("add.rn.f32x2 %0, %1, %2;" : "=l"(r) : "l"(a), "l"(b)); return r;
}
__device__ __forceinline__ u64 fma2_(u64 a, u64 b, u64 c) {
    u64 r; asm("fma.rn.f32x2 %0, %1, %2, %3;" : "=l"(r) : "l"(a), "l"(b), "l"(c)); return r;
}

__device__ __forceinline__ u64 mk_evict_first_policy() {
    u64 p; asm("createpolicy.fractional.L2::evict_first.b64 %0, 1.0;" : "=l"(p));
    return p;
}

__device__ __forceinline__ void cp_async16_pol(float* smem_dst, const void* gsrc, u64 pol) {
    uint32_t s = (uint32_t)__cvta_generic_to_shared(smem_dst);
    asm volatile("cp.async.cg.shared.global.L2::cache_hint [%0], [%1], 16, %2;"
                 :: "r"(s), "l"(gsrc), "l"(pol) : "memory");
}

__global__ __launch_bounds__(THREADS, 24)
void kmap_kernel(const float* __restrict__ var,
                 const float* __restrict__ slider_lengths,
                 const float* __restrict__ scos_g,
                 const float* __restrict__ ssin_g,
                 const float* __restrict__ note_dist,
                 const float* __restrict__ tick_diff,
                 const float* __restrict__ start_pos,
                 const int*   __restrict__ is_slider,
                 float* __restrict__ out,
                 int B)
{
    __shared__ float  sBuf[BUF_FLOATS];
    __shared__ float4 s_wall[NGS];   // wl, wr, wt, wb
    __shared__ float4 s_rot[NGS];    // scos, ssin, sln, isl_flag
    __shared__ u64    s_l2[NGS], s_rr2[NGS], s_nr2[NGS];  // pre-splatted pairs
    __shared__ float2 s_p0;

    const int lane    = threadIdx.x;
    const int warpRow = blockIdx.x * 32;
    const int rows    = (B - warpRow) < 32 ? (B - warpRow) : 32;
    const u64 pol     = mk_evict_first_policy();   // streaming data: evict-first in L2

    // ---- async input copy FIRST (latency overlaps param init) ----
    if (rows == 32) {
        const float4* gin = reinterpret_cast<const float4*>(var + (size_t)warpRow * IN_COLS);
        #pragma unroll
        for (int it = 0; it < (32 * IN_COLS) / 128; ++it) {   // 10 x 16B per thread
            int j4 = it * 32 + lane;
            int e = j4 * 4;
            int r = e / IN_COLS;
            cp_async16_pol(sBuf + e + 4 * r, &gin[j4], pol);  // padded: r*44 + c
        }
        asm volatile("cp.async.commit_group;" ::: "memory");
    } else if (rows > 0) {
        for (int j = lane; j < rows * IN_COLS; j += 32) {
            int r = j / IN_COLS, c = j - r * IN_COLS;
            sBuf[r * IN_STRIDE + c] = var[(size_t)warpRow * IN_COLS + j];
        }
    }

    // ---- packed per-group params ----
    if (lane < NGS) {
        float l  = note_dist[lane];                       // LMUL = 1.0
        float rr = (tick_diff[lane] <= 1.0f) ? 0.0f : 1.0f;
        s_wall[lane] = make_float4(0.05f * 512.0f + 0.5f * l,
                                   0.95f * 512.0f - 0.5f * l,
                                   0.05f * 384.0f + 0.5f * l,
                                   0.95f * 384.0f - 0.5f * l);
        s_rot[lane]  = make_float4(scos_g[lane], ssin_g[lane],
                                   slider_lengths[lane],
                                   is_slider[lane] ? 1.0f : 0.0f);
        s_l2[lane]  = pk2(l, l);
        s_rr2[lane] = pk2(rr, rr);
        s_nr2[lane] = pk2(1.0f - rr, 1.0f - rr);
    }
    if (lane == 0) s_p0 = make_float2(start_pos[0], start_pos[1]);
    __syncwarp();

    if (rows == 32) {
        asm volatile("cp.async.wait_group 0;" ::: "memory");
        __syncwarp();

        // ---- stage inputs to registers (10 x LDS.128, conflict-free) ----
        float rin[IN_COLS];
        const float* rowp = sBuf + lane * IN_STRIDE;
        #pragma unroll
        for (int c = 0; c < IN_COLS / 4; ++c) {
            float4 t = *reinterpret_cast<const float4*>(rowp + 4 * c);
            rin[4*c+0] = t.x; rin[4*c+1] = t.y; rin[4*c+2] = t.z; rin[4*c+3] = t.w;
        }
        __syncwarp();   // all lanes staged before STS overwrites the overlay

        // ---- compute: packed f32x2 scan; k-pairs emitted as 3x STS.128 ----
        const u64 CA   = pk2(256.0f, 192.0f);            // rerand scale/offset
        const u64 CINV = pk2(1.0f / 512.0f, 1.0f / 384.0f);
        float* orow = sBuf + lane * OUT_COLS;            // raw stride 60
        float px = s_p0.x, py = s_p0.y;
        u64 pxy = pk2(px, py);
        #pragma unroll
        for (int kp = 0; kp < NGS / 2; ++kp) {
            float o[12];
            #pragma unroll
            for (int h = 0; h < 2; ++h) {
                const int k = 2 * kp + h;
                float4 wall = s_wall[k];
                float4 rot  = s_rot[k];
                u64 l2 = s_l2[k], rr2 = s_rr2[k], nr2 = s_nr2[k];

                float vk   = rin[k],           vkh  = rin[NGS + k];
                float v2k  = rin[2 * NGS + k], v2kh = rin[3 * NGS + k];

                float inv  = rsqrtf(fmaf(vk,  vk,  v2k  * v2k));
                float invh = rsqrtf(fmaf(vkh, vkh, v2kh * v2kh));
                u64 pv  = pk2(vk, v2k);
                u64 cs  = mul2(pv, pk2(inv, inv));               // (ck, sk)
                u64 csh = mul2(pk2(vkh, v2kh), pk2(invh, invh)); // (ckh, skh)

                float dx, dy; up2(mul2(l2, cs), dx, dy);
                float xd = (px < wall.x) ?  fabsf(dx)
                         : (px > wall.y) ? -fabsf(dx)
                         : ((px > wall.x) && (px < wall.y)) ? dx : 0.0f;
                float yd = (py < wall.z) ?  fabsf(dy)
                         : (py > wall.w) ? -fabsf(dy)
                         : ((py > wall.z) && (py < wall.w)) ? dy : 0.0f;

                u64 rer = fma2_(pv, CA, CA);                     // 256+256vk, 192+192v2k
                u64 xy  = fma2_(nr2, add2(pxy, pk2(xd, yd)), mul2(rr2, rer));
                u64 c01 = mul2(xy, CINV);
                pxy = xy;
                up2(xy, px, py);
                float c0, c1; up2(c01, c0, c1);

                float c2, c3, c4, c5;
                if (rot.w != 0.0f) {     // uniform per k
                    float ckh, skh; up2(csh, ckh, skh);
                    c2 = fmaf(ckh, rot.x, -(skh * rot.y));
                    c3 = fmaf(ckh, rot.y,  skh * rot.x);
                    up2(mul2(fma2_(csh, pk2(rot.z, rot.z), xy), CINV), c4, c5);
                } else {
                    up2(fma2_(nr2, cs, mul2(rr2, csh)), c2, c3);
                    c4 = c0; c5 = c1;
                }
                o[6*h+0] = c0; o[6*h+1] = c1; o[6*h+2] = c2;
                o[6*h+3] = c3; o[6*h+4] = c4; o[6*h+5] = c5;
            }
            float4* dst = reinterpret_cast<float4*>(orow + 12 * kp);  // 48B-aligned
            dst[0] = make_float4(o[0], o[1], o[2],  o[3]);
            dst[1] = make_float4(o[4], o[5], o[6],  o[7]);
            dst[2] = make_float4(o[8], o[9], o[10], o[11]);
        }

        // ---- single TMA bulk copy (evict-first), smem (raw layout) -> global ----
        asm volatile("fence.proxy.async.shared::cta;" ::: "memory");
        __syncwarp();
        if (lane == 0) {
            uint32_t s = (uint32_t)__cvta_generic_to_shared(sBuf);
            float* g = out + (size_t)warpRow * OUT_COLS;   // contiguous 7680B
            asm volatile("cp.async.bulk.global.shared::cta.bulk_group.L2::cache_hint "
                         "[%0], [%1], %2, %3;"
                         :: "l"(g), "r"(s), "n"(32 * OUT_COLS * 4), "l"(pol) : "memory");
            asm volatile("cp.async.bulk.commit_group;" ::: "memory");
            // .read: wait only until TMA has finished READING sBuf (minimal
            // requirement before smem recycling at block exit), not until the
            // global writes land — trims the block's exit tail.
            asm volatile("cp.async.bulk.wait_group.read 0;" ::: "memory");
        }
    } else if (lane < rows) {
        // ---- partial tile fallback: direct scalar global path ----
        const float* grow  = var + (size_t)(warpRow + lane) * IN_COLS;
        float*       gorow = out + (size_t)(warpRow + lane) * OUT_COLS;
        float px = s_p0.x, py = s_p0.y;
        #pragma unroll
        for (int k = 0; k < NGS; ++k) {
            float4 wall = s_wall[k];
            float4 rot  = s_rot[k];
            float l, dum, rr;
            up2(s_l2[k], l, dum);
            up2(s_rr2[k], rr, dum);
            float nr = 1.0f - rr;
            float vk   = grow[k];
            float vkh  = grow[NGS + k];
            float v2k  = grow[2 * NGS + k];
            float v2kh = grow[3 * NGS + k];
            float inv  = rsqrtf(fmaf(vk, vk, v2k * v2k));
            float ck   = vk  * inv,  sk  = v2k  * inv;
            float invh = rsqrtf(fmaf(vkh, vkh, v2kh * v2kh));
            float ckh  = vkh * invh, skh = v2kh * invh;
            float dx = l * ck, dy = l * sk;
            float xd = (px < wall.x) ?  fabsf(dx)
                     : (px > wall.y) ? -fabsf(dx)
                     : ((px > wall.x) && (px < wall.y)) ? dx : 0.0f;
            float yd = (py < wall.z) ?  fabsf(dy)
                     : (py > wall.w) ? -fabsf(dy)
                     : ((py > wall.z) && (py < wall.w)) ? dy : 0.0f;
            float x = rr * (256.0f + 256.0f * vk)  + nr * (px + xd);
            float y = rr * (192.0f + 192.0f * v2k) + nr * (py + yd);
            float c0 = x * (1.0f / 512.0f), c1 = y * (1.0f / 384.0f);
            float c2, c3, c4, c5;
            if (rot.w != 0.0f) {
                c2 = ckh * rot.x - skh * rot.y;
                c3 = ckh * rot.y + skh * rot.x;
                c4 = (x + ckh * rot.z) * (1.0f / 512.0f);
                c5 = (y + skh * rot.z) * (1.0f / 384.0f);
            } else {
                c2 = rr * ckh + nr * ck;
                c3 = rr * skh + nr * sk;
                c4 = c0; c5 = c1;
            }
            gorow[6*k+0] = c0; gorow[6*k+1] = c1; gorow[6*k+2] = c2;
            gorow[6*k+3] = c3; gorow[6*k+4] = c4; gorow[6*k+5] = c5;
            px = x; py = y;
        }
    }
}

extern "C" void kernel_launch(void* const* d_in, const int* in_sizes, int n_in,
                              void* d_out, int out_size)
{
    const float* var  = (const float*)d_in[0];
    const float* sln  = (const float*)d_in[1];
    const float* scos = (const float*)d_in[2];
    const float* ssin = (const float*)d_in[3];
    const float* nd   = (const float*)d_in[4];
    const float* td   = (const float*)d_in[5];
    const float* sp   = (const float*)d_in[6];
    const int*   isl  = (const int*)d_in[7];
    float* out = (float*)d_out;

    int B = in_sizes[0] / IN_COLS;
    int blocks = (B + 31) / 32;
    kmap_kernel<<<blocks, THREADS>>>(var, sln, scos, ssin, nd, td,
                                     sp, isl, out, B);
}